// round 16
// baseline (speedup 1.0000x reference)
#include <cuda_runtime.h>
#include <cuda_bf16.h>
#include <cstdint>

#define NN      50000
#define EE      800000
#define ET      850000
#define HID     128
#define HEADS   4
#define NB      64
#define LAYERS  3
#define LN_EPS  1e-5f
#define NEG_SLOPE 0.2f

#define SCAN_BLK 256
#define NBLK ((NN + SCAN_BLK - 1) / SCAN_BLK)   // 196

// ---------------- device scratch ----------------
__device__ float g_h[NN * HID];
__device__ float g_tmp[NN * HID];
__device__ float g_as[NN * HEADS];
__device__ float g_ad[NN * HEADS];
__device__ int   g_deg[NN];
__device__ int   g_off[NN + 1];
__device__ int   g_cur[NN];
__device__ int   g_bsum[NBLK];
__device__ int   g_csr_src[ET];
__device__ __nv_bfloat16 g_wT_hi[4 * HID * HID];  // [w][n][k] = W[k][n] hi
__device__ __nv_bfloat16 g_wT_lo[4 * HID * HID];

// ---------------- helpers ----------------
__device__ __forceinline__ float warpSum(float v) {
#pragma unroll
    for (int o = 16; o > 0; o >>= 1) v += __shfl_xor_sync(0xffffffffu, v, o);
    return v;
}
__device__ __forceinline__ float warpMax(float v) {
#pragma unroll
    for (int o = 16; o > 0; o >>= 1) v = fmaxf(v, __shfl_xor_sync(0xffffffffu, v, o));
    return v;
}
__device__ __forceinline__ int warpSumI(int v) {
#pragma unroll
    for (int o = 16; o > 0; o >>= 1) v += __shfl_xor_sync(0xffffffffu, v, o);
    return v;
}
__device__ __forceinline__ int warpScanIncl(int x, int lane) {
#pragma unroll
    for (int o = 1; o < 32; o <<= 1) {
        int t = __shfl_up_sync(0xffffffffu, x, o);
        if (lane >= o) x += t;
    }
    return x;
}
__device__ __forceinline__ float lrelu(float x) { return x > 0.f ? x : NEG_SLOPE * x; }
__device__ __forceinline__ float silu(float x) { return x / (1.f + __expf(-x)); }

__device__ __forceinline__ void mma_bf16(float* c, const uint32_t* a, const uint32_t* b) {
    asm volatile(
        "mma.sync.aligned.m16n8k16.row.col.f32.bf16.bf16.f32 "
        "{%0,%1,%2,%3},{%4,%5,%6,%7},{%8,%9},{%0,%1,%2,%3};"
        : "+f"(c[0]), "+f"(c[1]), "+f"(c[2]), "+f"(c[3])
        : "r"(a[0]), "r"(a[1]), "r"(a[2]), "r"(a[3]), "r"(b[0]), "r"(b[1]));
}

// ---------------- weight prep: W^T split into bf16 hi/lo ----------------
__global__ void wprep_kernel(const float* __restrict__ W0, const float* __restrict__ Wg,
                             __nv_bfloat16* __restrict__ bh, __nv_bfloat16* __restrict__ bl) {
    int i = blockIdx.x * blockDim.x + threadIdx.x;
    if (i >= 4 * HID * HID) return;
    int w = i >> 14, rem = i & 16383, n = rem >> 7, k = rem & 127;
    const float* src = (w == 0) ? W0 : (Wg + (w - 1) * HID * HID);
    float v = src[k * HID + n];
    __nv_bfloat16 hi = __float2bfloat16(v);
    bh[i] = hi;
    bl[i] = __float2bfloat16(v - __bfloat162float(hi));
}

// ---------------- CSR build ----------------
__global__ void zero_deg_kernel(int* deg) {
    int i = blockIdx.x * blockDim.x + threadIdx.x;
    if (i < NN) deg[i] = 0;
}
__global__ void count_deg_kernel(const int* __restrict__ ei, int* __restrict__ deg) {
    int i = blockIdx.x * blockDim.x + threadIdx.x;
    if (i >= ET) return;
    int dst = (i < EE) ? ei[EE + i] : (i - EE);
    atomicAdd(&deg[dst], 1);
}
__global__ void scan_part_kernel(const int* __restrict__ deg, int* __restrict__ bsum) {
    __shared__ int sh[SCAN_BLK / 32];
    int tid = threadIdx.x, lane = tid & 31, w = tid >> 5;
    int i = blockIdx.x * SCAN_BLK + tid;
    int v = (i < NN) ? deg[i] : 0;
    int s = warpSumI(v);
    if (lane == 0) sh[w] = s;
    __syncthreads();
    if (w == 0) {
        int t = (lane < SCAN_BLK / 32) ? sh[lane] : 0;
        t = warpSumI(t);
        if (lane == 0) bsum[blockIdx.x] = t;
    }
}
__global__ void scan_top_kernel(int* __restrict__ bsum, int* __restrict__ off) {
    __shared__ int sh[8];
    int tid = threadIdx.x, lane = tid & 31, w = tid >> 5;
    int v = (tid < NBLK) ? bsum[tid] : 0;
    int x = warpScanIncl(v, lane);
    if (lane == 31) sh[w] = x;
    __syncthreads();
    if (w == 0) {
        int t = (lane < 8) ? sh[lane] : 0;
        t = warpScanIncl(t, lane);
        if (lane < 8) sh[lane] = t;
    }
    __syncthreads();
    int incl = x + (w ? sh[w - 1] : 0);
    if (tid < NBLK) bsum[tid] = incl - v;
    if (tid == NBLK - 1) off[NN] = incl;
}
__global__ void scan_add_kernel(const int* __restrict__ deg, const int* __restrict__ bsum,
                                int* __restrict__ off, int* __restrict__ cur) {
    __shared__ int sh[SCAN_BLK / 32];
    int tid = threadIdx.x, lane = tid & 31, w = tid >> 5;
    int i = blockIdx.x * SCAN_BLK + tid;
    int v = (i < NN) ? deg[i] : 0;
    int x = warpScanIncl(v, lane);
    if (lane == 31) sh[w] = x;
    __syncthreads();
    if (w == 0) {
        int t = (lane < SCAN_BLK / 32) ? sh[lane] : 0;
        t = warpScanIncl(t, lane);
        if (lane < SCAN_BLK / 32) sh[lane] = t;
    }
    __syncthreads();
    int excl = x - v + (w ? sh[w - 1] : 0) + bsum[blockIdx.x];
    if (i < NN) {
        off[i] = excl;
        cur[i] = excl;
    }
}
__global__ void scatter_kernel(const int* __restrict__ ei, int* __restrict__ cur,
                               int* __restrict__ csr_src) {
    int i = blockIdx.x * blockDim.x + threadIdx.x;
    if (i >= ET) return;
    int src, dst;
    if (i < EE) { src = ei[i]; dst = ei[EE + i]; }
    else        { src = i - EE; dst = i - EE; }
    int pos = atomicAdd(&cur[dst], 1);
    csr_src[pos] = src;
}

// ---------------- bf16 HMMA GEMM, 2-term split: C = ah*(bh+bl) --------------
#define U32STR 68
#define REGION (128 * U32STR * 4)          // 34816 B
#define SM_A_HI 0
#define SM_B_HI REGION
#define SM_B_LO (2 * REGION)
#define GEMM_SMEM (3 * REGION)             // 104448 B
#define CSTR 132

__global__ __launch_bounds__(512, 1)
void gemm_tc_kernel(const float* __restrict__ A, const __nv_bfloat16* __restrict__ Bh,
                    const __nv_bfloat16* __restrict__ Bl, int M, int mode,
                    const float* __restrict__ p0, const float* __restrict__ p1,
                    const float* __restrict__ p2, float* __restrict__ out,
                    float* __restrict__ as_, float* __restrict__ ad_) {
    extern __shared__ char smem[];
    uint32_t* uAh = (uint32_t*)(smem + SM_A_HI);
    uint32_t* uBh = (uint32_t*)(smem + SM_B_HI);
    uint32_t* uBl = (uint32_t*)(smem + SM_B_LO);
    float* Cs = (float*)smem;

    const int tid = threadIdx.x, wid = tid >> 5, lane = tid & 31;
    const int g = lane >> 2, tig = lane & 3;
    const int rm = (wid >> 2) * 32;
    const int cn = (wid & 3) * 32;
    const int row0 = blockIdx.x * 128;

#pragma unroll
    for (int i = 0; i < 8; i++) {
        int idx = tid + i * 512;
        int r = idx >> 5;
        int c = (idx & 31) << 2;
        int gr = row0 + r;
        float4 v = make_float4(0.f, 0.f, 0.f, 0.f);
        if (gr < M) v = *(const float4*)(A + (long)gr * 128 + c);
        __nv_bfloat162 q0 = __floats2bfloat162_rn(v.x, v.y);
        __nv_bfloat162 q1 = __floats2bfloat162_rn(v.z, v.w);
        int o = r * U32STR + (c >> 1);
        uAh[o] = *(uint32_t*)&q0;
        uAh[o + 1] = *(uint32_t*)&q1;
    }
    const uint4* bhu = (const uint4*)Bh;
    const uint4* blu = (const uint4*)Bl;
#pragma unroll
    for (int i = 0; i < 4; i++) {
        int idx = tid + i * 512;
        int n = idx >> 4;
        int kg = (idx & 15) << 3;
        int o = n * U32STR + (kg >> 1);
        *(uint4*)(uBh + o) = bhu[idx];
        *(uint4*)(uBl + o) = blu[idx];
    }
    __syncthreads();

    float acc[2][4][4];
#pragma unroll
    for (int i = 0; i < 2; i++)
#pragma unroll
        for (int j = 0; j < 4; j++)
#pragma unroll
            for (int k = 0; k < 4; k++) acc[i][j][k] = 0.f;

#pragma unroll
    for (int ks = 0; ks < 8; ks++) {
        const int k32 = ks * 8 + tig;
        uint32_t ah[2][4], bh[4][2], bl[4][2];
#pragma unroll
        for (int mf = 0; mf < 2; mf++) {
            int r = rm + mf * 16 + g;
            ah[mf][0] = uAh[r * U32STR + k32];
            ah[mf][1] = uAh[(r + 8) * U32STR + k32];
            ah[mf][2] = uAh[r * U32STR + k32 + 4];
            ah[mf][3] = uAh[(r + 8) * U32STR + k32 + 4];
        }
#pragma unroll
        for (int nf = 0; nf < 4; nf++) {
            int c = cn + nf * 8 + g;
            bh[nf][0] = uBh[c * U32STR + k32];
            bh[nf][1] = uBh[c * U32STR + k32 + 4];
            bl[nf][0] = uBl[c * U32STR + k32];
            bl[nf][1] = uBl[c * U32STR + k32 + 4];
        }
#pragma unroll
        for (int mf = 0; mf < 2; mf++)
#pragma unroll
            for (int nf = 0; nf < 4; nf++) {
                mma_bf16(acc[mf][nf], ah[mf], bl[nf]);
                mma_bf16(acc[mf][nf], ah[mf], bh[nf]);
            }
    }
    __syncthreads();

#pragma unroll
    for (int mf = 0; mf < 2; mf++) {
        int r = rm + mf * 16 + g;
#pragma unroll
        for (int nf = 0; nf < 4; nf++) {
            int c = cn + nf * 8 + tig * 2;
            *(float2*)(Cs + r * CSTR + c) = make_float2(acc[mf][nf][0], acc[mf][nf][1]);
            *(float2*)(Cs + (r + 8) * CSTR + c) = make_float2(acc[mf][nf][2], acc[mf][nf][3]);
        }
    }
    __syncthreads();

    const int col = lane * 4;
#pragma unroll 1
    for (int i = 0; i < 8; i++) {
        int r = wid * 8 + i;
        int gr = row0 + r;
        if (gr >= M) break;
        float4 v = *(const float4*)(Cs + r * CSTR + col);
        if (mode == 0) {
            float4 b4 = *(const float4*)(p0 + col);
            v.x += b4.x; v.y += b4.y; v.z += b4.z; v.w += b4.w;
            float mu = warpSum(v.x + v.y + v.z + v.w) * (1.f / 128.f);
            float dx = v.x - mu, dy = v.y - mu, dz = v.z - mu, dw = v.w - mu;
            float var = warpSum(dx * dx + dy * dy + dz * dz + dw * dw) * (1.f / 128.f);
            float rs = rsqrtf(var + LN_EPS);
            float4 gv = *(const float4*)(p1 + col);
            float4 bv = *(const float4*)(p2 + col);
            float y;
            y = dx * rs * gv.x + bv.x; v.x = silu(y);
            y = dy * rs * gv.y + bv.y; v.y = silu(y);
            y = dz * rs * gv.z + bv.z; v.z = silu(y);
            y = dw * rs * gv.w + bv.w; v.w = silu(y);
            *(float4*)(out + (long)gr * 128 + col) = v;
        } else {
            *(float4*)(out + (long)gr * 128 + col) = v;
            float4 w1 = *(const float4*)(p0 + col);
            float4 w2 = *(const float4*)(p1 + col);
            float sa = v.x * w1.x + v.y * w1.y + v.z * w1.z + v.w * w1.w;
            float sd = v.x * w2.x + v.y * w2.y + v.z * w2.z + v.w * w2.w;
#pragma unroll
            for (int o = 4; o > 0; o >>= 1) {
                sa += __shfl_xor_sync(0xffffffffu, sa, o);
                sd += __shfl_xor_sync(0xffffffffu, sd, o);
            }
            float a0 = __shfl_sync(0xffffffffu, sa, 0);
            float a1 = __shfl_sync(0xffffffffu, sa, 8);
            float a2 = __shfl_sync(0xffffffffu, sa, 16);
            float a3 = __shfl_sync(0xffffffffu, sa, 24);
            float d0 = __shfl_sync(0xffffffffu, sd, 0);
            float d1 = __shfl_sync(0xffffffffu, sd, 8);
            float d2 = __shfl_sync(0xffffffffu, sd, 16);
            float d3 = __shfl_sync(0xffffffffu, sd, 24);
            if (lane == 0) {
                *(float4*)(as_ + gr * 4) = make_float4(a0, a1, a2, a3);
                *(float4*)(ad_ + gr * 4) = make_float4(d0, d1, d2, d3);
            }
        }
    }
}

// -------- GAT aggregate: reg-cached softmax + smem alphas for pass 3 -------
// Pass-3 weight = 1 broadcast LDS instead of LDG+lrelu+exp (bit-identical values).
__global__ void gat_aggregate_kernel(const float* __restrict__ hh, const float* __restrict__ a_s,
                                     const float* __restrict__ a_d, const int* __restrict__ off,
                                     const int* __restrict__ csr_src, const float* __restrict__ bg,
                                     const float* __restrict__ gg, const float* __restrict__ bgg,
                                     float* __restrict__ h) {
    __shared__ float s_alpha[8][32][4];
    int n = (blockIdx.x * blockDim.x + threadIdx.x) >> 5;
    if (n >= NN) return;
    int lane = threadIdx.x & 31;
    float (*aslot)[4] = s_alpha[(threadIdx.x >> 5) & 7];
    int beg = off[n], end = off[n + 1];
    int cnt = end - beg;

    float4 adv = *(const float4*)(a_d + n * 4);
    // chunk-0 edge logits in registers (deg<=32 common case)
    float e0 = -1e30f, e1 = -1e30f, e2 = -1e30f, e3 = -1e30f;
    if (lane < cnt) {
        int s = csr_src[beg + lane];
        float4 asv = *(const float4*)(a_s + s * 4);
        e0 = lrelu(asv.x + adv.x);
        e1 = lrelu(asv.y + adv.y);
        e2 = lrelu(asv.z + adv.z);
        e3 = lrelu(asv.w + adv.w);
    }
    float lm0 = e0, lm1 = e1, lm2 = e2, lm3 = e3;
    for (int j = beg + 32 + lane; j < end; j += 32) {   // rare: deg > 32
        int s = csr_src[j];
        float4 asv = *(const float4*)(a_s + s * 4);
        lm0 = fmaxf(lm0, lrelu(asv.x + adv.x));
        lm1 = fmaxf(lm1, lrelu(asv.y + adv.y));
        lm2 = fmaxf(lm2, lrelu(asv.z + adv.z));
        lm3 = fmaxf(lm3, lrelu(asv.w + adv.w));
    }
    float m0 = warpMax(lm0), m1 = warpMax(lm1), m2 = warpMax(lm2), m3 = warpMax(lm3);

    float p0 = (lane < cnt) ? __expf(e0 - m0) : 0.f;
    float p1 = (lane < cnt) ? __expf(e1 - m1) : 0.f;
    float p2 = (lane < cnt) ? __expf(e2 - m2) : 0.f;
    float p3 = (lane < cnt) ? __expf(e3 - m3) : 0.f;
    float s0 = p0, s1 = p1, s2 = p2, s3 = p3;
    for (int j = beg + 32 + lane; j < end; j += 32) {   // rare
        int s = csr_src[j];
        float4 asv = *(const float4*)(a_s + s * 4);
        s0 += __expf(lrelu(asv.x + adv.x) - m0);
        s1 += __expf(lrelu(asv.y + adv.y) - m1);
        s2 += __expf(lrelu(asv.z + adv.z) - m2);
        s3 += __expf(lrelu(asv.w + adv.w) - m3);
    }
    s0 = warpSum(s0); s1 = warpSum(s1); s2 = warpSum(s2); s3 = warpSum(s3);
    float i0 = 1.f / s0, i1 = 1.f / s1, i2 = 1.f / s2, i3 = 1.f / s3;

    // chunk-0 normalized alphas -> smem (one float4 per lane)
    *(float4*)aslot[lane] = make_float4(p0 * i0, p1 * i1, p2 * i2, p3 * i3);
    __syncwarp();

    const int hd = lane >> 3;
    const int col = lane * 4;
    float4 acc = make_float4(0.f, 0.f, 0.f, 0.f);
    // pass 3, chunk 0: uniform csr load + broadcast LDS weight + coalesced gather
    int n0 = min(cnt, 32);
    for (int j = 0; j < n0; j++) {
        int s = csr_src[beg + j];
        float w = aslot[j][hd];
        float4 v = *(const float4*)(hh + (long)s * 128 + col);
        acc.x += v.x * w; acc.y += v.y * w; acc.z += v.z * w; acc.w += v.w * w;
    }
    // extra chunks (deg > 32, rare)
    for (int base = beg + 32; base < end; base += 32) {
        int ne = min(end - base, 32);
        float4 av = make_float4(0.f, 0.f, 0.f, 0.f);
        if (lane < ne) {
            int s2 = csr_src[base + lane];
            float4 asv = *(const float4*)(a_s + s2 * 4);
            av.x = __expf(lrelu(asv.x + adv.x) - m0) * i0;
            av.y = __expf(lrelu(asv.y + adv.y) - m1) * i1;
            av.z = __expf(lrelu(asv.z + adv.z) - m2) * i2;
            av.w = __expf(lrelu(asv.w + adv.w) - m3) * i3;
        }
        __syncwarp();
        *(float4*)aslot[lane] = av;
        __syncwarp();
        for (int j = 0; j < ne; j++) {
            int s = csr_src[base + j];
            float w = aslot[j][hd];
            float4 v = *(const float4*)(hh + (long)s * 128 + col);
            acc.x += v.x * w; acc.y += v.y * w; acc.z += v.z * w; acc.w += v.w * w;
        }
    }
    // un-normalized scale: chunk-0 alphas already include inv; chunk-0 weights
    // applied with inv, matching round-14 (w = exp(e-m)*inv) exactly.

    float4 bgv = *(const float4*)(bg + col);
    acc.x += bgv.x; acc.y += bgv.y; acc.z += bgv.z; acc.w += bgv.w;
    float mu = warpSum(acc.x + acc.y + acc.z + acc.w) * (1.f / 128.f);
    float dx = acc.x - mu, dy = acc.y - mu, dz = acc.z - mu, dw = acc.w - mu;
    float var = warpSum(dx * dx + dy * dy + dz * dz + dw * dw) * (1.f / 128.f);
    float r = rsqrtf(var + LN_EPS);
    float4 gv  = *(const float4*)(gg + col);
    float4 bv  = *(const float4*)(bgg + col);
    float4 old = *(const float4*)(h + (long)n * 128 + col);
    float y;
    y = dx * r * gv.x + bv.x; acc.x = silu(y) + old.x;
    y = dy * r * gv.y + bv.y; acc.y = silu(y) + old.y;
    y = dz * r * gv.z + bv.z; acc.z = silu(y) + old.z;
    y = dw * r * gv.w + bv.w; acc.w = silu(y) + old.w;
    *(float4*)(h + (long)n * 128 + col) = acc;
}

// -------- fused pool (sorted batch) + projection + LN + SiLU, 512 thr -----
__global__ __launch_bounds__(512)
void pool_final_kernel(const float* __restrict__ h, const int* __restrict__ batch,
                       const float* __restrict__ Wp, const float* __restrict__ bp,
                       const float* __restrict__ gp, const float* __restrict__ bep,
                       float* __restrict__ out) {
    __shared__ float part[4][128];
    __shared__ float p[128];
    __shared__ float accv[128];
    __shared__ float sh[4];
    __shared__ int bounds[2];
    int b = blockIdx.x, t = threadIdx.x;
    int col = t & 127, q = t >> 7;
    int lane = t & 31;
    if (t < 2) {
        int target = b + t;
        int lo = 0, hi = NN;
        while (lo < hi) {
            int mid = (lo + hi) >> 1;
            if (batch[mid] < target) lo = mid + 1; else hi = mid;
        }
        bounds[t] = lo;
    }
    __syncthreads();
    int lo = bounds[0], hi = bounds[1];
    float s = 0.f;
    for (int n = lo + q; n < hi; n += 4) s += h[(long)n * 128 + col];
    part[q][col] = s;
    __syncthreads();
    if (t < 128) {
        float c = (float)(hi - lo > 0 ? hi - lo : 1);
        p[t] = (part[0][t] + part[1][t] + part[2][t] + part[3][t]) / c;
    }
    __syncthreads();
    float ap = 0.f;
#pragma unroll 8
    for (int k = q * 32; k < q * 32 + 32; k++) ap += p[k] * Wp[k * 128 + col];
    part[q][col] = ap;
    __syncthreads();
    if (t < 128) accv[t] = part[0][t] + part[1][t] + part[2][t] + part[3][t] + bp[t];
    __syncthreads();
    float a = accv[col];
    float v = warpSum(a);
    if (t < 128 && lane == 0) sh[t >> 5] = v;
    __syncthreads();
    float mu = (sh[0] + sh[1] + sh[2] + sh[3]) * (1.f / 128.f);
    float d = a - mu;
    v = warpSum(d * d);
    __syncthreads();
    if (t < 128 && lane == 0) sh[t >> 5] = v;
    __syncthreads();
    float var = (sh[0] + sh[1] + sh[2] + sh[3]) * (1.f / 128.f);
    if (t < 128) {
        float r = rsqrtf(var + LN_EPS);
        float y = d * r * gp[t] + bep[t];
        out[b * 128 + t] = silu(y);
    }
}

// ---------------- launch ----------------
extern "C" void kernel_launch(void* const* d_in, const int* in_sizes, int n_in,
                              void* d_out, int out_size) {
    const float* x       = (const float*)d_in[0];
    const int*   ei      = (const int*)d_in[1];
    const int*   batch   = (const int*)d_in[2];
    const float* W0      = (const float*)d_in[3];
    const float* b0      = (const float*)d_in[4];
    const float* g0      = (const float*)d_in[5];
    const float* be0     = (const float*)d_in[6];
    const float* Wg      = (const float*)d_in[7];
    const float* att_src = (const float*)d_in[8];
    const float* att_dst = (const float*)d_in[9];
    const float* bg      = (const float*)d_in[10];
    const float* gg      = (const float*)d_in[11];
    const float* bgg     = (const float*)d_in[12];
    const float* Wp      = (const float*)d_in[13];
    const float* bp      = (const float*)d_in[14];
    const float* gp      = (const float*)d_in[15];
    const float* bep     = (const float*)d_in[16];
    float* out = (float*)d_out;

    float *h, *tmp, *as_, *ad_;
    int *deg, *off, *cur, *csr, *bsum;
    __nv_bfloat16 *wh, *wl;
    cudaGetSymbolAddress((void**)&h, g_h);
    cudaGetSymbolAddress((void**)&tmp, g_tmp);
    cudaGetSymbolAddress((void**)&as_, g_as);
    cudaGetSymbolAddress((void**)&ad_, g_ad);
    cudaGetSymbolAddress((void**)&deg, g_deg);
    cudaGetSymbolAddress((void**)&off, g_off);
    cudaGetSymbolAddress((void**)&cur, g_cur);
    cudaGetSymbolAddress((void**)&csr, g_csr_src);
    cudaGetSymbolAddress((void**)&bsum, g_bsum);
    cudaGetSymbolAddress((void**)&wh, g_wT_hi);
    cudaGetSymbolAddress((void**)&wl, g_wT_lo);

    cudaFuncSetAttribute(gemm_tc_kernel, cudaFuncAttributeMaxDynamicSharedMemorySize,
                         GEMM_SMEM);
    const int GEMM_GRID = (NN + 127) / 128;

    // launch order: index 3 = encoder GEMM (ncu capture slot)
    wprep_kernel<<<(4 * HID * HID + 255) / 256, 256>>>(W0, Wg, wh, wl);       // 0
    zero_deg_kernel<<<(NN + 255) / 256, 256>>>(deg);                          // 1
    count_deg_kernel<<<(ET + 255) / 256, 256>>>(ei, deg);                     // 2
    gemm_tc_kernel<<<GEMM_GRID, 512, GEMM_SMEM>>>(x, wh, wl, NN, 0,           // 3
                                                  b0, g0, be0, h, nullptr, nullptr);
    scan_part_kernel<<<NBLK, SCAN_BLK>>>(deg, bsum);                          // 4
    scan_top_kernel<<<1, 256>>>(bsum, off);                                   // 5
    scan_add_kernel<<<NBLK, SCAN_BLK>>>(deg, bsum, off, cur);                 // 6
    scatter_kernel<<<(ET + 255) / 256, 256>>>(ei, cur, csr);                  // 7

    for (int l = 0; l < LAYERS; l++) {
        gemm_tc_kernel<<<GEMM_GRID, 512, GEMM_SMEM>>>(
            h, wh + (l + 1) * HID * HID, wl + (l + 1) * HID * HID, NN, 1,
            att_src + l * 128, att_dst + l * 128, nullptr, tmp, as_, ad_);
        gat_aggregate_kernel<<<(NN * 32 + 255) / 256, 256>>>(
            tmp, as_, ad_, off, csr, bg + l * 128, gg + l * 128, bgg + l * 128, h);
    }

    pool_final_kernel<<<NB, 512>>>(h, batch, Wp, bp, gp, bep, out);
}

// round 17
// speedup vs baseline: 1.1250x; 1.1250x over previous
#include <cuda_runtime.h>
#include <cuda_bf16.h>
#include <cstdint>

#define NN      50000
#define EE      800000
#define ET      850000
#define HID     128
#define HEADS   4
#define NB      64
#define LAYERS  3
#define LN_EPS  1e-5f
#define NEG_SLOPE 0.2f

#define SCAN_BLK 256
#define NBLK ((NN + SCAN_BLK - 1) / SCAN_BLK)   // 196

// ---------------- device scratch ----------------
__device__ float g_h[NN * HID];
__device__ float g_tmp[NN * HID];
__device__ float g_as[NN * HEADS];
__device__ float g_ad[NN * HEADS];
__device__ int   g_deg[NN];
__device__ int   g_off[NN + 1];
__device__ int   g_cur[NN];
__device__ int   g_bsum[NBLK];
__device__ int   g_csr_src[ET];
__device__ __nv_bfloat16 g_wT_hi[4 * HID * HID];  // [w][n][k] = W[k][n] hi
__device__ __nv_bfloat16 g_wT_lo[4 * HID * HID];

// ---------------- helpers ----------------
__device__ __forceinline__ float warpSum(float v) {
#pragma unroll
    for (int o = 16; o > 0; o >>= 1) v += __shfl_xor_sync(0xffffffffu, v, o);
    return v;
}
__device__ __forceinline__ float warpMax(float v) {
#pragma unroll
    for (int o = 16; o > 0; o >>= 1) v = fmaxf(v, __shfl_xor_sync(0xffffffffu, v, o));
    return v;
}
__device__ __forceinline__ int warpSumI(int v) {
#pragma unroll
    for (int o = 16; o > 0; o >>= 1) v += __shfl_xor_sync(0xffffffffu, v, o);
    return v;
}
__device__ __forceinline__ int warpScanIncl(int x, int lane) {
#pragma unroll
    for (int o = 1; o < 32; o <<= 1) {
        int t = __shfl_up_sync(0xffffffffu, x, o);
        if (lane >= o) x += t;
    }
    return x;
}
__device__ __forceinline__ float lrelu(float x) { return x > 0.f ? x : NEG_SLOPE * x; }
__device__ __forceinline__ float silu(float x) { return x / (1.f + __expf(-x)); }

__device__ __forceinline__ void mma_bf16(float* c, const uint32_t* a, const uint32_t* b) {
    asm volatile(
        "mma.sync.aligned.m16n8k16.row.col.f32.bf16.bf16.f32 "
        "{%0,%1,%2,%3},{%4,%5,%6,%7},{%8,%9},{%0,%1,%2,%3};"
        : "+f"(c[0]), "+f"(c[1]), "+f"(c[2]), "+f"(c[3])
        : "r"(a[0]), "r"(a[1]), "r"(a[2]), "r"(a[3]), "r"(b[0]), "r"(b[1]));
}

// ---------------- weight prep: W^T split into bf16 hi/lo (+ deg zeroing) ----
__global__ void wprep_kernel(const float* __restrict__ W0, const float* __restrict__ Wg,
                             __nv_bfloat16* __restrict__ bh, __nv_bfloat16* __restrict__ bl,
                             int* __restrict__ deg) {
    int i = blockIdx.x * blockDim.x + threadIdx.x;
    if (i < NN) deg[i] = 0;
    if (i >= 4 * HID * HID) return;
    int w = i >> 14, rem = i & 16383, n = rem >> 7, k = rem & 127;
    const float* src = (w == 0) ? W0 : (Wg + (w - 1) * HID * HID);
    float v = src[k * HID + n];
    __nv_bfloat16 hi = __float2bfloat16(v);
    bh[i] = hi;
    bl[i] = __float2bfloat16(v - __bfloat162float(hi));
}

// ---------------- CSR build ----------------
__global__ void count_deg_kernel(const int* __restrict__ ei, int* __restrict__ deg) {
    int i = blockIdx.x * blockDim.x + threadIdx.x;
    if (i >= ET) return;
    int dst = (i < EE) ? ei[EE + i] : (i - EE);
    atomicAdd(&deg[dst], 1);
}
__global__ void scan_part_kernel(const int* __restrict__ deg, int* __restrict__ bsum) {
    __shared__ int sh[SCAN_BLK / 32];
    int tid = threadIdx.x, lane = tid & 31, w = tid >> 5;
    int i = blockIdx.x * SCAN_BLK + tid;
    int v = (i < NN) ? deg[i] : 0;
    int s = warpSumI(v);
    if (lane == 0) sh[w] = s;
    __syncthreads();
    if (w == 0) {
        int t = (lane < SCAN_BLK / 32) ? sh[lane] : 0;
        t = warpSumI(t);
        if (lane == 0) bsum[blockIdx.x] = t;
    }
}
__global__ void scan_top_kernel(int* __restrict__ bsum, int* __restrict__ off) {
    __shared__ int sh[8];
    int tid = threadIdx.x, lane = tid & 31, w = tid >> 5;
    int v = (tid < NBLK) ? bsum[tid] : 0;
    int x = warpScanIncl(v, lane);
    if (lane == 31) sh[w] = x;
    __syncthreads();
    if (w == 0) {
        int t = (lane < 8) ? sh[lane] : 0;
        t = warpScanIncl(t, lane);
        if (lane < 8) sh[lane] = t;
    }
    __syncthreads();
    int incl = x + (w ? sh[w - 1] : 0);
    if (tid < NBLK) bsum[tid] = incl - v;
    if (tid == NBLK - 1) off[NN] = incl;
}
__global__ void scan_add_kernel(const int* __restrict__ deg, const int* __restrict__ bsum,
                                int* __restrict__ off, int* __restrict__ cur) {
    __shared__ int sh[SCAN_BLK / 32];
    int tid = threadIdx.x, lane = tid & 31, w = tid >> 5;
    int i = blockIdx.x * SCAN_BLK + tid;
    int v = (i < NN) ? deg[i] : 0;
    int x = warpScanIncl(v, lane);
    if (lane == 31) sh[w] = x;
    __syncthreads();
    if (w == 0) {
        int t = (lane < SCAN_BLK / 32) ? sh[lane] : 0;
        t = warpScanIncl(t, lane);
        if (lane < SCAN_BLK / 32) sh[lane] = t;
    }
    __syncthreads();
    int excl = x - v + (w ? sh[w - 1] : 0) + bsum[blockIdx.x];
    if (i < NN) {
        off[i] = excl;
        cur[i] = excl;
    }
}
__global__ void scatter_kernel(const int* __restrict__ ei, int* __restrict__ cur,
                               int* __restrict__ csr_src) {
    int i = blockIdx.x * blockDim.x + threadIdx.x;
    if (i >= ET) return;
    int src, dst;
    if (i < EE) { src = ei[i]; dst = ei[EE + i]; }
    else        { src = i - EE; dst = i - EE; }
    int pos = atomicAdd(&cur[dst], 1);
    csr_src[pos] = src;
}

// ---------------- bf16 HMMA GEMM, 2-term split: C = ah*(bh+bl) --------------
#define U32STR 68
#define REGION (128 * U32STR * 4)          // 34816 B
#define SM_A_HI 0
#define SM_B_HI REGION
#define SM_B_LO (2 * REGION)
#define GEMM_SMEM (3 * REGION)             // 104448 B
#define CSTR 132

__global__ __launch_bounds__(512, 1)
void gemm_tc_kernel(const float* __restrict__ A, const __nv_bfloat16* __restrict__ Bh,
                    const __nv_bfloat16* __restrict__ Bl, int M, int mode,
                    const float* __restrict__ p0, const float* __restrict__ p1,
                    const float* __restrict__ p2, float* __restrict__ out,
                    float* __restrict__ as_, float* __restrict__ ad_) {
    extern __shared__ char smem[];
    uint32_t* uAh = (uint32_t*)(smem + SM_A_HI);
    uint32_t* uBh = (uint32_t*)(smem + SM_B_HI);
    uint32_t* uBl = (uint32_t*)(smem + SM_B_LO);
    float* Cs = (float*)smem;

    const int tid = threadIdx.x, wid = tid >> 5, lane = tid & 31;
    const int g = lane >> 2, tig = lane & 3;
    const int rm = (wid >> 2) * 32;
    const int cn = (wid & 3) * 32;
    const int row0 = blockIdx.x * 128;

#pragma unroll
    for (int i = 0; i < 8; i++) {
        int idx = tid + i * 512;
        int r = idx >> 5;
        int c = (idx & 31) << 2;
        int gr = row0 + r;
        float4 v = make_float4(0.f, 0.f, 0.f, 0.f);
        if (gr < M) v = *(const float4*)(A + (long)gr * 128 + c);
        __nv_bfloat162 q0 = __floats2bfloat162_rn(v.x, v.y);
        __nv_bfloat162 q1 = __floats2bfloat162_rn(v.z, v.w);
        int o = r * U32STR + (c >> 1);
        uAh[o] = *(uint32_t*)&q0;
        uAh[o + 1] = *(uint32_t*)&q1;
    }
    const uint4* bhu = (const uint4*)Bh;
    const uint4* blu = (const uint4*)Bl;
#pragma unroll
    for (int i = 0; i < 4; i++) {
        int idx = tid + i * 512;
        int n = idx >> 4;
        int kg = (idx & 15) << 3;
        int o = n * U32STR + (kg >> 1);
        *(uint4*)(uBh + o) = bhu[idx];
        *(uint4*)(uBl + o) = blu[idx];
    }
    __syncthreads();

    float acc[2][4][4];
#pragma unroll
    for (int i = 0; i < 2; i++)
#pragma unroll
        for (int j = 0; j < 4; j++)
#pragma unroll
            for (int k = 0; k < 4; k++) acc[i][j][k] = 0.f;

#pragma unroll
    for (int ks = 0; ks < 8; ks++) {
        const int k32 = ks * 8 + tig;
        uint32_t ah[2][4], bh[4][2], bl[4][2];
#pragma unroll
        for (int mf = 0; mf < 2; mf++) {
            int r = rm + mf * 16 + g;
            ah[mf][0] = uAh[r * U32STR + k32];
            ah[mf][1] = uAh[(r + 8) * U32STR + k32];
            ah[mf][2] = uAh[r * U32STR + k32 + 4];
            ah[mf][3] = uAh[(r + 8) * U32STR + k32 + 4];
        }
#pragma unroll
        for (int nf = 0; nf < 4; nf++) {
            int c = cn + nf * 8 + g;
            bh[nf][0] = uBh[c * U32STR + k32];
            bh[nf][1] = uBh[c * U32STR + k32 + 4];
            bl[nf][0] = uBl[c * U32STR + k32];
            bl[nf][1] = uBl[c * U32STR + k32 + 4];
        }
#pragma unroll
        for (int mf = 0; mf < 2; mf++)
#pragma unroll
            for (int nf = 0; nf < 4; nf++) {
                mma_bf16(acc[mf][nf], ah[mf], bl[nf]);
                mma_bf16(acc[mf][nf], ah[mf], bh[nf]);
            }
    }
    __syncthreads();

#pragma unroll
    for (int mf = 0; mf < 2; mf++) {
        int r = rm + mf * 16 + g;
#pragma unroll
        for (int nf = 0; nf < 4; nf++) {
            int c = cn + nf * 8 + tig * 2;
            *(float2*)(Cs + r * CSTR + c) = make_float2(acc[mf][nf][0], acc[mf][nf][1]);
            *(float2*)(Cs + (r + 8) * CSTR + c) = make_float2(acc[mf][nf][2], acc[mf][nf][3]);
        }
    }
    __syncthreads();

    const int col = lane * 4;
#pragma unroll 1
    for (int i = 0; i < 8; i++) {
        int r = wid * 8 + i;
        int gr = row0 + r;
        if (gr >= M) break;
        float4 v = *(const float4*)(Cs + r * CSTR + col);
        if (mode == 0) {
            float4 b4 = *(const float4*)(p0 + col);
            v.x += b4.x; v.y += b4.y; v.z += b4.z; v.w += b4.w;
            float mu = warpSum(v.x + v.y + v.z + v.w) * (1.f / 128.f);
            float dx = v.x - mu, dy = v.y - mu, dz = v.z - mu, dw = v.w - mu;
            float var = warpSum(dx * dx + dy * dy + dz * dz + dw * dw) * (1.f / 128.f);
            float rs = rsqrtf(var + LN_EPS);
            float4 gv = *(const float4*)(p1 + col);
            float4 bv = *(const float4*)(p2 + col);
            float y;
            y = dx * rs * gv.x + bv.x; v.x = silu(y);
            y = dy * rs * gv.y + bv.y; v.y = silu(y);
            y = dz * rs * gv.z + bv.z; v.z = silu(y);
            y = dw * rs * gv.w + bv.w; v.w = silu(y);
            *(float4*)(out + (long)gr * 128 + col) = v;
        } else {
            *(float4*)(out + (long)gr * 128 + col) = v;
            float4 w1 = *(const float4*)(p0 + col);
            float4 w2 = *(const float4*)(p1 + col);
            float sa = v.x * w1.x + v.y * w1.y + v.z * w1.z + v.w * w1.w;
            float sd = v.x * w2.x + v.y * w2.y + v.z * w2.z + v.w * w2.w;
#pragma unroll
            for (int o = 4; o > 0; o >>= 1) {
                sa += __shfl_xor_sync(0xffffffffu, sa, o);
                sd += __shfl_xor_sync(0xffffffffu, sd, o);
            }
            float a0 = __shfl_sync(0xffffffffu, sa, 0);
            float a1 = __shfl_sync(0xffffffffu, sa, 8);
            float a2 = __shfl_sync(0xffffffffu, sa, 16);
            float a3 = __shfl_sync(0xffffffffu, sa, 24);
            float d0 = __shfl_sync(0xffffffffu, sd, 0);
            float d1 = __shfl_sync(0xffffffffu, sd, 8);
            float d2 = __shfl_sync(0xffffffffu, sd, 16);
            float d3 = __shfl_sync(0xffffffffu, sd, 24);
            if (lane == 0) {
                *(float4*)(as_ + gr * 4) = make_float4(a0, a1, a2, a3);
                *(float4*)(ad_ + gr * 4) = make_float4(d0, d1, d2, d3);
            }
        }
    }
}

// -------- GAT aggregate (round-14 winner): reg-cached stats, LDG-recompute
// pass 3, LN + SiLU + residual. Warp per dst node.
__global__ void gat_aggregate_kernel(const float* __restrict__ hh, const float* __restrict__ a_s,
                                     const float* __restrict__ a_d, const int* __restrict__ off,
                                     const int* __restrict__ csr_src, const float* __restrict__ bg,
                                     const float* __restrict__ gg, const float* __restrict__ bgg,
                                     float* __restrict__ h) {
    int n = (blockIdx.x * blockDim.x + threadIdx.x) >> 5;
    if (n >= NN) return;
    int lane = threadIdx.x & 31;
    int beg = off[n], end = off[n + 1];
    int cnt = end - beg;

    float4 adv = *(const float4*)(a_d + n * 4);
    float e0 = -1e30f, e1 = -1e30f, e2 = -1e30f, e3 = -1e30f;
    if (lane < cnt) {
        int s = csr_src[beg + lane];
        float4 asv = *(const float4*)(a_s + s * 4);
        e0 = lrelu(asv.x + adv.x);
        e1 = lrelu(asv.y + adv.y);
        e2 = lrelu(asv.z + adv.z);
        e3 = lrelu(asv.w + adv.w);
    }
    float lm0 = e0, lm1 = e1, lm2 = e2, lm3 = e3;
    for (int j = beg + 32 + lane; j < end; j += 32) {
        int s = csr_src[j];
        float4 asv = *(const float4*)(a_s + s * 4);
        lm0 = fmaxf(lm0, lrelu(asv.x + adv.x));
        lm1 = fmaxf(lm1, lrelu(asv.y + adv.y));
        lm2 = fmaxf(lm2, lrelu(asv.z + adv.z));
        lm3 = fmaxf(lm3, lrelu(asv.w + adv.w));
    }
    float m0 = warpMax(lm0), m1 = warpMax(lm1), m2 = warpMax(lm2), m3 = warpMax(lm3);

    float s0 = (lane < cnt) ? __expf(e0 - m0) : 0.f;
    float s1 = (lane < cnt) ? __expf(e1 - m1) : 0.f;
    float s2 = (lane < cnt) ? __expf(e2 - m2) : 0.f;
    float s3 = (lane < cnt) ? __expf(e3 - m3) : 0.f;
    for (int j = beg + 32 + lane; j < end; j += 32) {
        int s = csr_src[j];
        float4 asv = *(const float4*)(a_s + s * 4);
        s0 += __expf(lrelu(asv.x + adv.x) - m0);
        s1 += __expf(lrelu(asv.y + adv.y) - m1);
        s2 += __expf(lrelu(asv.z + adv.z) - m2);
        s3 += __expf(lrelu(asv.w + adv.w) - m3);
    }
    s0 = warpSum(s0); s1 = warpSum(s1); s2 = warpSum(s2); s3 = warpSum(s3);

    int hd = lane >> 3;
    float mh   = (hd == 0) ? m0 : (hd == 1) ? m1 : (hd == 2) ? m2 : m3;
    float adh  = (hd == 0) ? adv.x : (hd == 1) ? adv.y : (hd == 2) ? adv.z : adv.w;
    float invh = 1.f / ((hd == 0) ? s0 : (hd == 1) ? s1 : (hd == 2) ? s2 : s3);

    const int col = lane * 4;
    float4 acc = make_float4(0.f, 0.f, 0.f, 0.f);
    for (int j = beg; j < end; j++) {
        int s = csr_src[j];
        float w = __expf(lrelu(a_s[s * 4 + hd] + adh) - mh) * invh;
        float4 v = *(const float4*)(hh + (long)s * 128 + col);
        acc.x += v.x * w; acc.y += v.y * w; acc.z += v.z * w; acc.w += v.w * w;
    }
    float4 bgv = *(const float4*)(bg + col);
    acc.x += bgv.x; acc.y += bgv.y; acc.z += bgv.z; acc.w += bgv.w;
    float mu = warpSum(acc.x + acc.y + acc.z + acc.w) * (1.f / 128.f);
    float dx = acc.x - mu, dy = acc.y - mu, dz = acc.z - mu, dw = acc.w - mu;
    float var = warpSum(dx * dx + dy * dy + dz * dz + dw * dw) * (1.f / 128.f);
    float r = rsqrtf(var + LN_EPS);
    float4 gv  = *(const float4*)(gg + col);
    float4 bv  = *(const float4*)(bgg + col);
    float4 old = *(const float4*)(h + (long)n * 128 + col);
    float y;
    y = dx * r * gv.x + bv.x; acc.x = silu(y) + old.x;
    y = dy * r * gv.y + bv.y; acc.y = silu(y) + old.y;
    y = dz * r * gv.z + bv.z; acc.z = silu(y) + old.z;
    y = dw * r * gv.w + bv.w; acc.w = silu(y) + old.w;
    *(float4*)(h + (long)n * 128 + col) = acc;
}

// -------- fused pool (sorted batch) + projection + LN + SiLU, 512 thr -----
__global__ __launch_bounds__(512)
void pool_final_kernel(const float* __restrict__ h, const int* __restrict__ batch,
                       const float* __restrict__ Wp, const float* __restrict__ bp,
                       const float* __restrict__ gp, const float* __restrict__ bep,
                       float* __restrict__ out) {
    __shared__ float part[4][128];
    __shared__ float p[128];
    __shared__ float accv[128];
    __shared__ float sh[4];
    __shared__ int bounds[2];
    int b = blockIdx.x, t = threadIdx.x;
    int col = t & 127, q = t >> 7;
    int lane = t & 31;
    if (t < 2) {
        int target = b + t;
        int lo = 0, hi = NN;
        while (lo < hi) {
            int mid = (lo + hi) >> 1;
            if (batch[mid] < target) lo = mid + 1; else hi = mid;
        }
        bounds[t] = lo;
    }
    __syncthreads();
    int lo = bounds[0], hi = bounds[1];
    float s = 0.f;
    for (int n = lo + q; n < hi; n += 4) s += h[(long)n * 128 + col];
    part[q][col] = s;
    __syncthreads();
    if (t < 128) {
        float c = (float)(hi - lo > 0 ? hi - lo : 1);
        p[t] = (part[0][t] + part[1][t] + part[2][t] + part[3][t]) / c;
    }
    __syncthreads();
    float ap = 0.f;
#pragma unroll 8
    for (int k = q * 32; k < q * 32 + 32; k++) ap += p[k] * Wp[k * 128 + col];
    part[q][col] = ap;
    __syncthreads();
    if (t < 128) accv[t] = part[0][t] + part[1][t] + part[2][t] + part[3][t] + bp[t];
    __syncthreads();
    float a = accv[col];
    float v = warpSum(a);
    if (t < 128 && lane == 0) sh[t >> 5] = v;
    __syncthreads();
    float mu = (sh[0] + sh[1] + sh[2] + sh[3]) * (1.f / 128.f);
    float d = a - mu;
    v = warpSum(d * d);
    __syncthreads();
    if (t < 128 && lane == 0) sh[t >> 5] = v;
    __syncthreads();
    float var = (sh[0] + sh[1] + sh[2] + sh[3]) * (1.f / 128.f);
    if (t < 128) {
        float r = rsqrtf(var + LN_EPS);
        float y = d * r * gp[t] + bep[t];
        out[b * 128 + t] = silu(y);
    }
}

// ---------------- launch ----------------
extern "C" void kernel_launch(void* const* d_in, const int* in_sizes, int n_in,
                              void* d_out, int out_size) {
    const float* x       = (const float*)d_in[0];
    const int*   ei      = (const int*)d_in[1];
    const int*   batch   = (const int*)d_in[2];
    const float* W0      = (const float*)d_in[3];
    const float* b0      = (const float*)d_in[4];
    const float* g0      = (const float*)d_in[5];
    const float* be0     = (const float*)d_in[6];
    const float* Wg      = (const float*)d_in[7];
    const float* att_src = (const float*)d_in[8];
    const float* att_dst = (const float*)d_in[9];
    const float* bg      = (const float*)d_in[10];
    const float* gg      = (const float*)d_in[11];
    const float* bgg     = (const float*)d_in[12];
    const float* Wp      = (const float*)d_in[13];
    const float* bp      = (const float*)d_in[14];
    const float* gp      = (const float*)d_in[15];
    const float* bep     = (const float*)d_in[16];
    float* out = (float*)d_out;

    float *h, *tmp, *as_, *ad_;
    int *deg, *off, *cur, *csr, *bsum;
    __nv_bfloat16 *wh, *wl;
    cudaGetSymbolAddress((void**)&h, g_h);
    cudaGetSymbolAddress((void**)&tmp, g_tmp);
    cudaGetSymbolAddress((void**)&as_, g_as);
    cudaGetSymbolAddress((void**)&ad_, g_ad);
    cudaGetSymbolAddress((void**)&deg, g_deg);
    cudaGetSymbolAddress((void**)&off, g_off);
    cudaGetSymbolAddress((void**)&cur, g_cur);
    cudaGetSymbolAddress((void**)&csr, g_csr_src);
    cudaGetSymbolAddress((void**)&bsum, g_bsum);
    cudaGetSymbolAddress((void**)&wh, g_wT_hi);
    cudaGetSymbolAddress((void**)&wl, g_wT_lo);

    cudaFuncSetAttribute(gemm_tc_kernel, cudaFuncAttributeMaxDynamicSharedMemorySize,
                         GEMM_SMEM);
    const int GEMM_GRID = (NN + 127) / 128;

    // launch order: index 2 = encoder GEMM? keep GEMM at index 3 slot: insert
    // scan_part after count to preserve capture alignment used before.
    wprep_kernel<<<(4 * HID * HID + 255) / 256, 256>>>(W0, Wg, wh, wl, deg);  // 0
    count_deg_kernel<<<(ET + 255) / 256, 256>>>(ei, deg);                     // 1
    scan_part_kernel<<<NBLK, SCAN_BLK>>>(deg, bsum);                          // 2
    gemm_tc_kernel<<<GEMM_GRID, 512, GEMM_SMEM>>>(x, wh, wl, NN, 0,           // 3
                                                  b0, g0, be0, h, nullptr, nullptr);
    scan_top_kernel<<<1, 256>>>(bsum, off);                                   // 4
    scan_add_kernel<<<NBLK, SCAN_BLK>>>(deg, bsum, off, cur);                 // 5
    scatter_kernel<<<(ET + 255) / 256, 256>>>(ei, cur, csr);                  // 6

    for (int l = 0; l < LAYERS; l++) {
        gemm_tc_kernel<<<GEMM_GRID, 512, GEMM_SMEM>>>(
            h, wh + (l + 1) * HID * HID, wl + (l + 1) * HID * HID, NN, 1,
            att_src + l * 128, att_dst + l * 128, nullptr, tmp, as_, ad_);
        gat_aggregate_kernel<<<(NN * 32 + 255) / 256, 256>>>(
            tmp, as_, ad_, off, csr, bg + l * 128, gg + l * 128, bgg + l * 128, h);
    }

    pool_final_kernel<<<NB, 512>>>(h, batch, Wp, bp, gp, bep, out);
}